// round 11
// baseline (speedup 1.0000x reference)
#include <cuda_runtime.h>
#include <cstdint>

#define NJ    24
#define NP    32768
#define NF    42
#define NR    16
#define DIN   126
#define HID   32
#define NIND  18
#define NOUTC 144

#define NKT   18           // K tiles (K padded to 144 = 3 * 48)
#define NWARP 8            // warps per block
#define NTILES 8           // tiles per block; tile = 128 pts (8 warps x 16)

// shared layout (floats). Per-warp scratch (16x52) is TIME-SHARED by:
//   V chunk (16x52) -> H (16x36) -> Ost (16x36)
#define OFF_VO   0                         // 8 warps * 16*52   = 6656
#define OFF_W1F  6656                      // 18kt*4nt*32*2     = 4608
#define OFF_W2F  11264                     // 4kt*16nt*32*2     = 4096
#define OFF_SF   15360                     // [c][r][48]        = 2304
#define OFF_B1   17664                     // 32
#define OFF_B2   17696                     // 128
#define SMEM_FLOATS 17824                  // 71296 bytes -> 3 blocks/SM

__device__ __forceinline__ uint32_t tf32r(float x) {
    uint32_t r; asm("cvt.rna.tf32.f32 %0, %1;" : "=r"(r) : "f"(x)); return r;
}

__device__ __forceinline__ void mma_tf32(float c[4], uint32_t a0, uint32_t a1,
                                         uint32_t a2, uint32_t a3,
                                         uint32_t b0, uint32_t b1) {
    asm volatile(
        "mma.sync.aligned.m16n8k8.row.col.f32.tf32.tf32.f32 "
        "{%0,%1,%2,%3}, {%4,%5,%6,%7}, {%8,%9}, {%0,%1,%2,%3};\n"
        : "+f"(c[0]), "+f"(c[1]), "+f"(c[2]), "+f"(c[3])
        : "r"(a0), "r"(a1), "r"(a2), "r"(a3), "r"(b0), "r"(b1));
}

extern "C" __global__ void __launch_bounds__(256)
v3d_mma_kernel(const float* __restrict__ pts,
               const float* __restrict__ feature,
               const float* __restrict__ ind,
               const float* __restrict__ w1,
               const float* __restrict__ b1,
               const float* __restrict__ w2,
               const float* __restrict__ b2,
               float* __restrict__ out)
{
    extern __shared__ float sm[];
    float* sfeat = sm + OFF_SF;
    float* b1s   = sm + OFF_B1;
    float* b2s   = sm + OFF_B2;
    uint32_t* w1f = (uint32_t*)(sm + OFF_W1F);
    uint32_t* w2f = (uint32_t*)(sm + OFF_W2F);

    const int j    = blockIdx.y;
    const int tid  = threadIdx.x;
    const int lane = tid & 31;
    const int warp = tid >> 5;

    // ---------------- Stage per-volume constants (once per block) ----------------
    if (tid < HID) b1s[tid] = b1[j * HID + tid];
    if (tid < 128) b2s[tid] = (tid < DIN) ? b2[j * DIN + tid] : 0.0f;

    {   // W1 fragments over padded K=144 (col k = c*48+f), [kt][nt][lane]{b0,b1}
        const float* w1g = w1 + j * (DIN * HID);
        for (int idx = tid; idx < NKT * 128; idx += 256) {
            int kt = idx >> 7, rem = idx & 127;
            int nt = rem >> 5, ln = rem & 31;
            int tg = ln & 3, gg = ln >> 2;
            int n  = nt * 8 + gg;
            uint32_t v2[2];
            #pragma unroll
            for (int s = 0; s < 2; ++s) {
                int k = kt * 8 + tg + 4 * s;
                int c = k / 48, f = k - c * 48;
                v2[s] = (f < NF) ? tf32r(w1g[(f * 3 + c) * HID + n]) : 0u;
            }
            *(uint2*)(w1f + idx * 2) = make_uint2(v2[0], v2[1]);
        }
    }
    {   // W2 fragments: [kt2][nt][lane]{b0,b1}, N padded 126->128
        const float* w2g = w2 + j * (HID * DIN);
        for (int idx = tid; idx < 2048; idx += 256) {
            int kt2 = idx >> 9, rem = idx & 511;
            int nt = rem >> 5, ln = rem & 31;
            int tg = ln & 3, gg = ln >> 2;
            int k = kt2 * 8 + tg, n = nt * 8 + gg;
            uint32_t x = (n < DIN) ? tf32r(w2g[k * DIN + n])       : 0u;
            uint32_t y = (n < DIN) ? tf32r(w2g[(k + 4) * DIN + n]) : 0u;
            *(uint2*)(w2f + idx * 2) = make_uint2(x, y);
        }
    }
    {   // features [f][r][c] -> [c][r][f] (48-padded, f-contiguous)
        for (int idx = tid; idx < 3 * NR * 48; idx += 256) sfeat[idx] = 0.0f;
        __syncthreads();
        const float* fg = feature + j * (NF * NR * 3);
        for (int idx = tid; idx < NF * NR * 3; idx += 256) {
            int f = idx / 48;
            int rr = (idx - f * 48) / 3;
            int c = idx - f * 48 - rr * 3;
            sfeat[(c * NR + rr) * 48 + f] = fg[idx];
        }
    }
    __syncthreads();

    float*    Vw = sm + OFF_VO + warp * (16 * 52);
    uint32_t* Vu = (uint32_t*)Vw;
    uint32_t* Hu = Vu;                    // H aliases V chunk region (time-shared)

    const int tig  = lane & 3;
    const int g    = lane >> 2;
    const int pt_l = lane & 15;
    const int half = lane >> 4;

    // ================= Tile loop: 8 tiles of 128 points =================
    #pragma unroll 1
    for (int t = 0; t < NTILES; ++t) {
        const int pw0 = (blockIdx.x * NTILES + t) * 128 + warp * 16;

        // point coords for this lane's point
        const float* pp = pts + ((size_t)j * NP + pw0 + pt_l) * 3;
        float pc0 = pp[0], pc1 = pp[1], pc2 = pp[2];

        // ---------------- ind_feature copy early (overlaps compute) ----------
        {
            float*       outg = out + ((size_t)j * NP + pw0) * NOUTC;
            const float* indg = ind + ((size_t)j * NP + pw0) * NIND;
            #pragma unroll 1
            for (int idx = lane; idx < 16 * NIND; idx += 32) {
                int ppt = idx / NIND;
                int cc  = idx - ppt * NIND;
                outg[ppt * NOUTC + cc] = indg[idx];
            }
        }

        // ---------------- Layer 1 with chunked V generation -------------------
        float c1r[4][4];
        #pragma unroll
        for (int nt = 0; nt < 4; ++nt)
            #pragma unroll
            for (int e = 0; e < 4; ++e) c1r[nt][e] = 0.0f;

        #pragma unroll
        for (int c = 0; c < 3; ++c) {
            // --- generate V chunk for axis c: 16 pts x 48 cols (f 0..41 + pad)
            float pcc = (c == 0) ? pc0 : ((c == 1) ? pc1 : pc2);
            float x = fminf(fmaxf(fmaf(pcc, 7.5f, 7.5f), 0.0f), 15.0f);
            int xi = (int)x; if (xi > NR - 2) xi = NR - 2;
            float wc = x - (float)xi;
            const float* row = sfeat + (c * NR + xi) * 48;
            uint32_t* vrow = Vu + pt_l * 52;

            if (half == 0) {
                #pragma unroll
                for (int i = 0; i < 6; ++i) {
                    float4 g0 = *(const float4*)(row + i * 4);
                    float4 g1 = *(const float4*)(row + 48 + i * 4);
                    uint4 vv;
                    vv.x = tf32r(fmaf(wc, g1.x - g0.x, g0.x));
                    vv.y = tf32r(fmaf(wc, g1.y - g0.y, g0.y));
                    vv.z = tf32r(fmaf(wc, g1.z - g0.z, g0.z));
                    vv.w = tf32r(fmaf(wc, g1.w - g0.w, g0.w));
                    *(uint4*)(vrow + i * 4) = vv;
                }
            } else {
                #pragma unroll
                for (int i = 0; i < 4; ++i) {
                    float4 g0 = *(const float4*)(row + 24 + i * 4);
                    float4 g1 = *(const float4*)(row + 72 + i * 4);
                    uint4 vv;
                    vv.x = tf32r(fmaf(wc, g1.x - g0.x, g0.x));
                    vv.y = tf32r(fmaf(wc, g1.y - g0.y, g0.y));
                    vv.z = tf32r(fmaf(wc, g1.z - g0.z, g0.z));
                    vv.w = tf32r(fmaf(wc, g1.w - g0.w, g0.w));
                    *(uint4*)(vrow + 24 + i * 4) = vv;
                }
                float2 g0 = *(const float2*)(row + 40);
                float2 g1 = *(const float2*)(row + 88);
                uint2 vv;
                vv.x = tf32r(fmaf(wc, g1.x - g0.x, g0.x));
                vv.y = tf32r(fmaf(wc, g1.y - g0.y, g0.y));
                *(uint2*)(vrow + 40) = vv;
                *(uint2*)(vrow + 42) = make_uint2(0u, 0u);         // pad f=42,43
                *(uint4*)(vrow + 44) = make_uint4(0u, 0u, 0u, 0u); // pad f=44..47
            }
            __syncwarp();

            // --- consume chunk: 6 kt steps
            #pragma unroll
            for (int ktl = 0; ktl < 6; ++ktl) {
                const uint32_t* va = Vu + g * 52 + ktl * 8 + tig;
                uint32_t a0 = va[0];
                uint32_t a1 = va[8 * 52];
                uint32_t a2 = va[4];
                uint32_t a3 = va[8 * 52 + 4];
                int kt = c * 6 + ktl;
                #pragma unroll
                for (int nt = 0; nt < 4; ++nt) {
                    uint2 b = *(const uint2*)(w1f + ((kt * 4 + nt) * 32 + lane) * 2);
                    mma_tf32(c1r[nt], a0, a1, a2, a3, b.x, b.y);
                }
            }
            __syncwarp();   // chunk buffer reused (next c, or H below)
        }

        // bias + relu + tf32 -> H (aliases V chunk region; safe post-sync)
        #pragma unroll
        for (int nt = 0; nt < 4; ++nt) {
            int n0 = nt * 8;
            float2 bb = *(const float2*)(b1s + n0 + 2 * tig);
            float h0 = fmaxf(c1r[nt][0] + bb.x, 0.0f);
            float h1 = fmaxf(c1r[nt][1] + bb.y, 0.0f);
            float h2 = fmaxf(c1r[nt][2] + bb.x, 0.0f);
            float h3 = fmaxf(c1r[nt][3] + bb.y, 0.0f);
            *(uint2*)(Hu + g * 36 + n0 + 2 * tig)       = make_uint2(tf32r(h0), tf32r(h1));
            *(uint2*)(Hu + (g + 8) * 36 + n0 + 2 * tig) = make_uint2(tf32r(h2), tf32r(h3));
        }
        __syncwarp();

        // ---------------- Layer 2 + staged epilogue ---------------------------
        uint32_t ha[16];
        #pragma unroll
        for (int kt2 = 0; kt2 < 4; ++kt2) {
            const uint32_t* hp = Hu + g * 36 + kt2 * 8 + tig;
            ha[kt2 * 4 + 0] = hp[0];
            ha[kt2 * 4 + 1] = hp[8 * 36];
            ha[kt2 * 4 + 2] = hp[4];
            ha[kt2 * 4 + 3] = hp[8 * 36 + 4];
        }
        __syncwarp();       // all lanes done reading H before Ost overwrites it

        float* outg = out + ((size_t)j * NP + pw0) * NOUTC;
        float* Ost  = Vw;   // reuse warp scratch again (aliases H, post-sync)

        #pragma unroll 1
        for (int r = 0; r < 4; ++r) {
            #pragma unroll
            for (int q = 0; q < 4; ++q) {
                int nt2 = r * 4 + q;
                float cc[4] = {0.0f, 0.0f, 0.0f, 0.0f};
                #pragma unroll
                for (int kt2 = 0; kt2 < 4; ++kt2) {
                    uint2 b = *(const uint2*)(w2f + ((kt2 * 16 + nt2) * 32 + lane) * 2);
                    mma_tf32(cc, ha[kt2 * 4 + 0], ha[kt2 * 4 + 1],
                                 ha[kt2 * 4 + 2], ha[kt2 * 4 + 3], b.x, b.y);
                }
                int chl = q * 8 + 2 * tig;          // 0..31 within round
                int ch  = r * 32 + chl;
                float2 bv = *(const float2*)(b2s + ch);
                *(float2*)(Ost + g * 36 + chl)       = make_float2(cc[0] + bv.x, cc[1] + bv.y);
                *(float2*)(Ost + (g + 8) * 36 + chl) = make_float2(cc[2] + bv.x, cc[3] + bv.y);
            }
            __syncwarp();
            int ch = r * 32 + lane;
            if (ch < DIN) {
                #pragma unroll 1
                for (int pt = 0; pt < 16; ++pt)
                    outg[pt * NOUTC + NIND + ch] = Ost[pt * 36 + lane];
            }
            __syncwarp();
        }
    }
}

extern "C" void kernel_launch(void* const* d_in, const int* in_sizes, int n_in,
                              void* d_out, int out_size)
{
    const float* pts     = (const float*)d_in[0];
    const float* feature = (const float*)d_in[1];
    const float* ind     = (const float*)d_in[2];
    const float* w1      = (const float*)d_in[3];
    const float* b1      = (const float*)d_in[4];
    const float* w2      = (const float*)d_in[5];
    const float* b2      = (const float*)d_in[6];
    float*       out     = (float*)d_out;

    const size_t smem = SMEM_FLOATS * sizeof(float);   // 71296 B -> 3 blocks/SM
    cudaFuncSetAttribute(v3d_mma_kernel,
                         cudaFuncAttributeMaxDynamicSharedMemorySize, (int)smem);

    dim3 grid(NP / (128 * NTILES), NJ);   // (32, 24)
    dim3 block(256);
    v3d_mma_kernel<<<grid, block, smem>>>(pts, feature, ind, w1, b1, w2, b2, out);
}

// round 12
// speedup vs baseline: 1.3004x; 1.3004x over previous
#include <cuda_runtime.h>
#include <cstdint>

#define NJ    24
#define NP    32768
#define NF    42
#define NR    16
#define DIN   126
#define HID   32
#define NIND  18
#define NOUTC 144

#define NKT   18           // K tiles (K padded to 144 = 3 * 48)
#define NTILES 4           // passes per block; pass = 256 pts (8 warps x 32)

// shared layout (floats). Per-warp scratch 32x52 time-shared: V chunk -> H(32x36)
#define OFF_VO   0                         // 8 warps * 32*52   = 13312
#define OFF_W1F  13312                     // 18kt*4nt*32*2     = 4608
#define OFF_W2F  17920                     // 4kt*16nt*32*2     = 4096
#define OFF_SF   22016                     // [c][r][48]        = 2304
#define OFF_B1   24320                     // 32
#define OFF_B2   24352                     // 128
#define SMEM_FLOATS 24480                  // 97920 B -> 2 blocks/SM (16 warps)

__device__ __forceinline__ uint32_t tf32r(float x) {
    uint32_t r; asm("cvt.rna.tf32.f32 %0, %1;" : "=r"(r) : "f"(x)); return r;
}

__device__ __forceinline__ void mma_tf32(float c[4], uint32_t a0, uint32_t a1,
                                         uint32_t a2, uint32_t a3,
                                         uint32_t b0, uint32_t b1) {
    asm volatile(
        "mma.sync.aligned.m16n8k8.row.col.f32.tf32.tf32.f32 "
        "{%0,%1,%2,%3}, {%4,%5,%6,%7}, {%8,%9}, {%0,%1,%2,%3};\n"
        : "+f"(c[0]), "+f"(c[1]), "+f"(c[2]), "+f"(c[3])
        : "r"(a0), "r"(a1), "r"(a2), "r"(a3), "r"(b0), "r"(b1));
}

extern "C" __global__ void __launch_bounds__(256)
v3d_mma_kernel(const float* __restrict__ pts,
               const float* __restrict__ feature,
               const float* __restrict__ ind,
               const float* __restrict__ w1,
               const float* __restrict__ b1,
               const float* __restrict__ w2,
               const float* __restrict__ b2,
               float* __restrict__ out)
{
    extern __shared__ float sm[];
    float* sfeat = sm + OFF_SF;
    float* b1s   = sm + OFF_B1;
    float* b2s   = sm + OFF_B2;
    uint32_t* w1f = (uint32_t*)(sm + OFF_W1F);
    uint32_t* w2f = (uint32_t*)(sm + OFF_W2F);

    const int j    = blockIdx.y;
    const int tid  = threadIdx.x;
    const int lane = tid & 31;
    const int warp = tid >> 5;

    // ---------------- Stage per-volume constants (once per block) ----------------
    if (tid < HID) b1s[tid] = b1[j * HID + tid];
    if (tid < 128) b2s[tid] = (tid < DIN) ? b2[j * DIN + tid] : 0.0f;

    {   // W1 fragments over padded K=144 (col k = c*48+f), [kt][nt][lane]{b0,b1}
        const float* w1g = w1 + j * (DIN * HID);
        for (int idx = tid; idx < NKT * 128; idx += 256) {
            int kt = idx >> 7, rem = idx & 127;
            int nt = rem >> 5, ln = rem & 31;
            int tg = ln & 3, gg = ln >> 2;
            int n  = nt * 8 + gg;
            uint32_t v2[2];
            #pragma unroll
            for (int s = 0; s < 2; ++s) {
                int k = kt * 8 + tg + 4 * s;
                int c = k / 48, f = k - c * 48;
                v2[s] = (f < NF) ? tf32r(w1g[(f * 3 + c) * HID + n]) : 0u;
            }
            *(uint2*)(w1f + idx * 2) = make_uint2(v2[0], v2[1]);
        }
    }
    {   // W2 fragments: [kt2][nt][lane]{b0,b1}, N padded 126->128
        const float* w2g = w2 + j * (HID * DIN);
        for (int idx = tid; idx < 2048; idx += 256) {
            int kt2 = idx >> 9, rem = idx & 511;
            int nt = rem >> 5, ln = rem & 31;
            int tg = ln & 3, gg = ln >> 2;
            int k = kt2 * 8 + tg, n = nt * 8 + gg;
            uint32_t x = (n < DIN) ? tf32r(w2g[k * DIN + n])       : 0u;
            uint32_t y = (n < DIN) ? tf32r(w2g[(k + 4) * DIN + n]) : 0u;
            *(uint2*)(w2f + idx * 2) = make_uint2(x, y);
        }
    }
    {   // features [f][r][c] -> [c][r][f] (48-padded, f-contiguous)
        for (int idx = tid; idx < 3 * NR * 48; idx += 256) sfeat[idx] = 0.0f;
        __syncthreads();
        const float* fg = feature + j * (NF * NR * 3);
        for (int idx = tid; idx < NF * NR * 3; idx += 256) {
            int f = idx / 48;
            int rr = (idx - f * 48) / 3;
            int c = idx - f * 48 - rr * 3;
            sfeat[(c * NR + rr) * 48 + f] = fg[idx];
        }
    }
    __syncthreads();

    uint32_t* Vu = (uint32_t*)(sm + OFF_VO) + warp * (32 * 52);
    uint32_t* Hu = Vu;                    // H aliases V chunk region (time-shared)

    const int tig = lane & 3;
    const int g   = lane >> 2;

    // ================= Pass loop: 4 passes of 256 points (32 per warp) ==========
    #pragma unroll 1
    for (int t = 0; t < NTILES; ++t) {
        const int pw0 = (blockIdx.x * NTILES + t) * 256 + warp * 32;

        // lane's point (lane = point index within warp's 32)
        const float* pp = pts + ((size_t)j * NP + pw0 + lane) * 3;
        float pc[3] = {pp[0], pp[1], pp[2]};

        // ---------------- ind_feature copy early (overlaps compute) ----------
        {
            float*       outg = out + ((size_t)j * NP + pw0) * NOUTC;
            const float* indg = ind + ((size_t)j * NP + pw0) * NIND;
            #pragma unroll 1
            for (int idx = lane; idx < 32 * NIND; idx += 32) {
                int ppt = idx / NIND;
                int cc  = idx - ppt * NIND;
                outg[ppt * NOUTC + cc] = indg[idx];
            }
        }

        // ---------------- Layer 1 with chunked V generation -------------------
        float c1r[2][4][4];
        #pragma unroll
        for (int m = 0; m < 2; ++m)
            #pragma unroll
            for (int nt = 0; nt < 4; ++nt)
                #pragma unroll
                for (int e = 0; e < 4; ++e) c1r[m][nt][e] = 0.0f;

        #pragma unroll
        for (int c = 0; c < 3; ++c) {
            // --- generate V chunk for axis c: 32 pts x 48 cols (lane = point)
            float x = fminf(fmaxf(fmaf(pc[c], 7.5f, 7.5f), 0.0f), 15.0f);
            int xi = (int)x; if (xi > NR - 2) xi = NR - 2;
            float wc = x - (float)xi;
            const float* row = sfeat + (c * NR + xi) * 48;
            uint32_t* vrow = Vu + lane * 52;

            #pragma unroll
            for (int i = 0; i < 12; ++i) {      // cols 0..47 (42..47 are zeros)
                float4 g0 = *(const float4*)(row + i * 4);
                float4 g1 = *(const float4*)(row + 48 + i * 4);
                uint4 vv;
                vv.x = tf32r(fmaf(wc, g1.x - g0.x, g0.x));
                vv.y = tf32r(fmaf(wc, g1.y - g0.y, g0.y));
                vv.z = tf32r(fmaf(wc, g1.z - g0.z, g0.z));
                vv.w = tf32r(fmaf(wc, g1.w - g0.w, g0.w));
                *(uint4*)(vrow + i * 4) = vv;
            }
            *(uint4*)(vrow + 48) = make_uint4(0u, 0u, 0u, 0u);   // pad 48..51
            __syncwarp();

            // --- consume chunk: 6 kt steps; each B fragment feeds BOTH m-tiles
            #pragma unroll
            for (int ktl = 0; ktl < 6; ++ktl) {
                int kt = c * 6 + ktl;
                uint2 b[4];
                #pragma unroll
                for (int nt = 0; nt < 4; ++nt)
                    b[nt] = *(const uint2*)(w1f + ((kt * 4 + nt) * 32 + lane) * 2);
                #pragma unroll
                for (int m = 0; m < 2; ++m) {
                    const uint32_t* va = Vu + (m * 16 + g) * 52 + ktl * 8 + tig;
                    uint32_t a0 = va[0];
                    uint32_t a1 = va[8 * 52];
                    uint32_t a2 = va[4];
                    uint32_t a3 = va[8 * 52 + 4];
                    #pragma unroll
                    for (int nt = 0; nt < 4; ++nt)
                        mma_tf32(c1r[m][nt], a0, a1, a2, a3, b[nt].x, b[nt].y);
                }
            }
            __syncwarp();   // chunk buffer reused (next c, or H below)
        }

        // bias + relu + tf32 -> H[pt][o] stride 36 (aliases V region, post-sync)
        #pragma unroll
        for (int m = 0; m < 2; ++m) {
            #pragma unroll
            for (int nt = 0; nt < 4; ++nt) {
                int n0 = nt * 8;
                float2 bb = *(const float2*)(b1s + n0 + 2 * tig);
                float h0 = fmaxf(c1r[m][nt][0] + bb.x, 0.0f);
                float h1 = fmaxf(c1r[m][nt][1] + bb.y, 0.0f);
                float h2 = fmaxf(c1r[m][nt][2] + bb.x, 0.0f);
                float h3 = fmaxf(c1r[m][nt][3] + bb.y, 0.0f);
                *(uint2*)(Hu + (m * 16 + g)     * 36 + n0 + 2 * tig) = make_uint2(tf32r(h0), tf32r(h1));
                *(uint2*)(Hu + (m * 16 + g + 8) * 36 + n0 + 2 * tig) = make_uint2(tf32r(h2), tf32r(h3));
            }
        }
        __syncwarp();

        // ---------------- Layer 2: A fragments for both m-tiles ---------------
        uint32_t ha[2][16];
        #pragma unroll
        for (int m = 0; m < 2; ++m)
            #pragma unroll
            for (int kt2 = 0; kt2 < 4; ++kt2) {
                const uint32_t* hp = Hu + (m * 16 + g) * 36 + kt2 * 8 + tig;
                ha[m][kt2 * 4 + 0] = hp[0];
                ha[m][kt2 * 4 + 1] = hp[8 * 36];
                ha[m][kt2 * 4 + 2] = hp[4];
                ha[m][kt2 * 4 + 3] = hp[8 * 36 + 4];
            }
        __syncwarp();       // V/H region free for next pass after this point

        // ---------------- Layer 2 MMAs + direct STG epilogue ------------------
        float* outb = out + ((size_t)j * NP + pw0) * NOUTC + NIND;
        #pragma unroll 2
        for (int nt2 = 0; nt2 < 16; ++nt2) {
            uint2 b[4];
            #pragma unroll
            for (int kt2 = 0; kt2 < 4; ++kt2)
                b[kt2] = *(const uint2*)(w2f + ((kt2 * 16 + nt2) * 32 + lane) * 2);
            int ch = nt2 * 8 + 2 * tig;
            #pragma unroll
            for (int m = 0; m < 2; ++m) {
                float cc[4] = {0.0f, 0.0f, 0.0f, 0.0f};
                #pragma unroll
                for (int kt2 = 0; kt2 < 4; ++kt2)
                    mma_tf32(cc, ha[m][kt2 * 4 + 0], ha[m][kt2 * 4 + 1],
                                 ha[m][kt2 * 4 + 2], ha[m][kt2 * 4 + 3],
                                 b[kt2].x, b[kt2].y);
                if (ch < DIN) {
                    float2 bv = *(const float2*)(b2s + ch);
                    *(float2*)(outb + (size_t)(m * 16 + g)     * NOUTC + ch) =
                        make_float2(cc[0] + bv.x, cc[1] + bv.y);
                    *(float2*)(outb + (size_t)(m * 16 + g + 8) * NOUTC + ch) =
                        make_float2(cc[2] + bv.x, cc[3] + bv.y);
                }
            }
        }
        __syncwarp();
    }
}

extern "C" void kernel_launch(void* const* d_in, const int* in_sizes, int n_in,
                              void* d_out, int out_size)
{
    const float* pts     = (const float*)d_in[0];
    const float* feature = (const float*)d_in[1];
    const float* ind     = (const float*)d_in[2];
    const float* w1      = (const float*)d_in[3];
    const float* b1      = (const float*)d_in[4];
    const float* w2      = (const float*)d_in[5];
    const float* b2      = (const float*)d_in[6];
    float*       out     = (float*)d_out;

    const size_t smem = SMEM_FLOATS * sizeof(float);   // 97920 B -> 2 blocks/SM
    cudaFuncSetAttribute(v3d_mma_kernel,
                         cudaFuncAttributeMaxDynamicSharedMemorySize, (int)smem);

    dim3 grid(NP / (256 * NTILES), NJ);   // (32, 24)
    dim3 block(256);
    v3d_mma_kernel<<<grid, block, smem>>>(pts, feature, ind, w1, b1, w2, b2, out);
}

// round 14
// speedup vs baseline: 1.5659x; 1.2042x over previous
#include <cuda_runtime.h>
#include <cstdint>

#define NJ    24
#define NP    32768
#define NF    42
#define NR    16
#define DIN   126
#define HID   32
#define NIND  18
#define NOUTC 144

#define NKT   18           // K tiles (K padded to 144 = 3 * 48)
#define NTILES 4           // passes per block; pass = 256 pts (8 warps x 32)
#define SFP   52           // feature-line stride (pad 48->52: kills xi bank conflicts)

// shared layout (floats). Per-warp scratch 32x52 time-shared: V chunk -> H(32x36)
#define OFF_VO   0                         // 8 warps * 32*52   = 13312
#define OFF_W1F  13312                     // 18kt*4nt*32*2     = 4608
#define OFF_W2F  17920                     // 4kt*16nt*32*2     = 4096
#define OFF_SF   22016                     // [c][r][SFP] 3*16*52 = 2496
#define OFF_B1   24512                     // 32
#define OFF_B2   24544                     // 128
#define SMEM_FLOATS 24672                  // 98688 B -> 2 blocks/SM (16 warps)

__device__ __forceinline__ uint32_t tf32r(float x) {
    uint32_t r; asm("cvt.rna.tf32.f32 %0, %1;" : "=r"(r) : "f"(x)); return r;
}

__device__ __forceinline__ void mma_tf32(float c[4], uint32_t a0, uint32_t a1,
                                         uint32_t a2, uint32_t a3,
                                         uint32_t b0, uint32_t b1) {
    asm volatile(
        "mma.sync.aligned.m16n8k8.row.col.f32.tf32.tf32.f32 "
        "{%0,%1,%2,%3}, {%4,%5,%6,%7}, {%8,%9}, {%0,%1,%2,%3};\n"
        : "+f"(c[0]), "+f"(c[1]), "+f"(c[2]), "+f"(c[3])
        : "r"(a0), "r"(a1), "r"(a2), "r"(a3), "r"(b0), "r"(b1));
}

extern "C" __global__ void __launch_bounds__(256)
v3d_mma_kernel(const float* __restrict__ pts,
               const float* __restrict__ feature,
               const float* __restrict__ ind,
               const float* __restrict__ w1,
               const float* __restrict__ b1,
               const float* __restrict__ w2,
               const float* __restrict__ b2,
               float* __restrict__ out)
{
    extern __shared__ float sm[];
    float* sfeat = sm + OFF_SF;
    float* b1s   = sm + OFF_B1;
    float* b2s   = sm + OFF_B2;
    uint32_t* w1f = (uint32_t*)(sm + OFF_W1F);
    uint32_t* w2f = (uint32_t*)(sm + OFF_W2F);

    const int j    = blockIdx.y;
    const int tid  = threadIdx.x;
    const int lane = tid & 31;
    const int warp = tid >> 5;

    // ---------------- Stage per-volume constants (once per block) ----------------
    if (tid < HID) b1s[tid] = b1[j * HID + tid];
    if (tid < 128) b2s[tid] = (tid < DIN) ? b2[j * DIN + tid] : 0.0f;

    {   // W1 fragments over padded K=144 (col k = c*48+f), [kt][nt][lane]{b0,b1}
        const float* w1g = w1 + j * (DIN * HID);
        for (int idx = tid; idx < NKT * 128; idx += 256) {
            int kt = idx >> 7, rem = idx & 127;
            int nt = rem >> 5, ln = rem & 31;
            int tg = ln & 3, gg = ln >> 2;
            int n  = nt * 8 + gg;
            uint32_t v2[2];
            #pragma unroll
            for (int s = 0; s < 2; ++s) {
                int k = kt * 8 + tg + 4 * s;
                int c = k / 48, f = k - c * 48;
                v2[s] = (f < NF) ? tf32r(w1g[(f * 3 + c) * HID + n]) : 0u;
            }
            *(uint2*)(w1f + idx * 2) = make_uint2(v2[0], v2[1]);
        }
    }
    {   // W2 fragments: [kt2][nt][lane]{b0,b1}, N padded 126->128
        const float* w2g = w2 + j * (HID * DIN);
        for (int idx = tid; idx < 2048; idx += 256) {
            int kt2 = idx >> 9, rem = idx & 511;
            int nt = rem >> 5, ln = rem & 31;
            int tg = ln & 3, gg = ln >> 2;
            int k = kt2 * 8 + tg, n = nt * 8 + gg;
            uint32_t x = (n < DIN) ? tf32r(w2g[k * DIN + n])       : 0u;
            uint32_t y = (n < DIN) ? tf32r(w2g[(k + 4) * DIN + n]) : 0u;
            *(uint2*)(w2f + idx * 2) = make_uint2(x, y);
        }
    }
    {   // features [f][r][c] -> [c][r][f], row stride SFP=52 (conflict-spread)
        for (int idx = tid; idx < 3 * NR * SFP; idx += 256) sfeat[idx] = 0.0f;
        __syncthreads();
        const float* fg = feature + j * (NF * NR * 3);
        for (int idx = tid; idx < NF * NR * 3; idx += 256) {
            int f = idx / 48;
            int rr = (idx - f * 48) / 3;
            int c = idx - f * 48 - rr * 3;
            sfeat[(c * NR + rr) * SFP + f] = fg[idx];
        }
    }
    __syncthreads();

    uint32_t* Vu = (uint32_t*)(sm + OFF_VO) + warp * (32 * 52);
    uint32_t* Hu = Vu;                    // H aliases V chunk region (time-shared)

    const int tig = lane & 3;
    const int g   = lane >> 2;

    // ================= Pass loop: 4 passes of 256 points (32 per warp) ==========
    #pragma unroll 1
    for (int t = 0; t < NTILES; ++t) {
        const int pw0 = (blockIdx.x * NTILES + t) * 256 + warp * 32;

        // lane's point (lane = point index within warp's 32)
        const float* pp = pts + ((size_t)j * NP + pw0 + lane) * 3;
        float pc[3] = {pp[0], pp[1], pp[2]};

        // ---------------- ind_feature copy early (overlaps compute) ----------
        {
            float*       outg = out + ((size_t)j * NP + pw0) * NOUTC;
            const float* indg = ind + ((size_t)j * NP + pw0) * NIND;
            #pragma unroll 1
            for (int idx = lane; idx < 32 * NIND; idx += 32) {
                int ppt = idx / NIND;
                int cc  = idx - ppt * NIND;
                outg[ppt * NOUTC + cc] = indg[idx];
            }
        }

        // ---------------- Layer 1 with chunked V generation -------------------
        float c1r[2][4][4];
        #pragma unroll
        for (int m = 0; m < 2; ++m)
            #pragma unroll
            for (int nt = 0; nt < 4; ++nt)
                #pragma unroll
                for (int e = 0; e < 4; ++e) c1r[m][nt][e] = 0.0f;

        #pragma unroll
        for (int c = 0; c < 3; ++c) {
            // --- generate V chunk for axis c: 32 pts x 48 cols (lane = point)
            float x = fminf(fmaxf(fmaf(pc[c], 7.5f, 7.5f), 0.0f), 15.0f);
            int xi = (int)x; if (xi > NR - 2) xi = NR - 2;
            float wc = x - (float)xi;
            const float* row = sfeat + (c * NR + xi) * SFP;
            uint32_t* vrow = Vu + lane * 52;

            #pragma unroll
            for (int i = 0; i < 12; ++i) {      // cols 0..47 (42..47 are zeros)
                float4 g0 = *(const float4*)(row + i * 4);
                float4 g1 = *(const float4*)(row + SFP + i * 4);
                uint4 vv;
                vv.x = tf32r(fmaf(wc, g1.x - g0.x, g0.x));
                vv.y = tf32r(fmaf(wc, g1.y - g0.y, g0.y));
                vv.z = tf32r(fmaf(wc, g1.z - g0.z, g0.z));
                vv.w = tf32r(fmaf(wc, g1.w - g0.w, g0.w));
                *(uint4*)(vrow + i * 4) = vv;
            }
            *(uint4*)(vrow + 48) = make_uint4(0u, 0u, 0u, 0u);   // pad 48..51
            __syncwarp();

            // --- consume chunk: 6 kt steps; each B fragment feeds BOTH m-tiles
            #pragma unroll
            for (int ktl = 0; ktl < 6; ++ktl) {
                int kt = c * 6 + ktl;
                uint2 b[4];
                #pragma unroll
                for (int nt = 0; nt < 4; ++nt)
                    b[nt] = *(const uint2*)(w1f + ((kt * 4 + nt) * 32 + lane) * 2);
                #pragma unroll
                for (int m = 0; m < 2; ++m) {
                    const uint32_t* va = Vu + (m * 16 + g) * 52 + ktl * 8 + tig;
                    uint32_t a0 = va[0];
                    uint32_t a1 = va[8 * 52];
                    uint32_t a2 = va[4];
                    uint32_t a3 = va[8 * 52 + 4];
                    #pragma unroll
                    for (int nt = 0; nt < 4; ++nt)
                        mma_tf32(c1r[m][nt], a0, a1, a2, a3, b[nt].x, b[nt].y);
                }
            }
            __syncwarp();   // chunk buffer reused (next c, or H below)
        }

        // bias + relu + tf32 -> H[pt][o] stride 36 (aliases V region, post-sync)
        #pragma unroll
        for (int m = 0; m < 2; ++m) {
            #pragma unroll
            for (int nt = 0; nt < 4; ++nt) {
                int n0 = nt * 8;
                float2 bb = *(const float2*)(b1s + n0 + 2 * tig);
                float h0 = fmaxf(c1r[m][nt][0] + bb.x, 0.0f);
                float h1 = fmaxf(c1r[m][nt][1] + bb.y, 0.0f);
                float h2 = fmaxf(c1r[m][nt][2] + bb.x, 0.0f);
                float h3 = fmaxf(c1r[m][nt][3] + bb.y, 0.0f);
                *(uint2*)(Hu + (m * 16 + g)     * 36 + n0 + 2 * tig) = make_uint2(tf32r(h0), tf32r(h1));
                *(uint2*)(Hu + (m * 16 + g + 8) * 36 + n0 + 2 * tig) = make_uint2(tf32r(h2), tf32r(h3));
            }
        }
        __syncwarp();

        // ---------------- Layer 2: A fragments for both m-tiles ---------------
        uint32_t ha[2][16];
        #pragma unroll
        for (int m = 0; m < 2; ++m)
            #pragma unroll
            for (int kt2 = 0; kt2 < 4; ++kt2) {
                const uint32_t* hp = Hu + (m * 16 + g) * 36 + kt2 * 8 + tig;
                ha[m][kt2 * 4 + 0] = hp[0];
                ha[m][kt2 * 4 + 1] = hp[8 * 36];
                ha[m][kt2 * 4 + 2] = hp[4];
                ha[m][kt2 * 4 + 3] = hp[8 * 36 + 4];
            }
        __syncwarp();       // V/H region free for next pass after this point

        // ---------------- Layer 2 MMAs + direct STG epilogue ------------------
        float* outb = out + ((size_t)j * NP + pw0) * NOUTC + NIND;
        #pragma unroll 2
        for (int nt2 = 0; nt2 < 16; ++nt2) {
            uint2 b[4];
            #pragma unroll
            for (int kt2 = 0; kt2 < 4; ++kt2)
                b[kt2] = *(const uint2*)(w2f + ((kt2 * 16 + nt2) * 32 + lane) * 2);
            int ch = nt2 * 8 + 2 * tig;
            #pragma unroll
            for (int m = 0; m < 2; ++m) {
                float cc[4] = {0.0f, 0.0f, 0.0f, 0.0f};
                #pragma unroll
                for (int kt2 = 0; kt2 < 4; ++kt2)
                    mma_tf32(cc, ha[m][kt2 * 4 + 0], ha[m][kt2 * 4 + 1],
                                 ha[m][kt2 * 4 + 2], ha[m][kt2 * 4 + 3],
                                 b[kt2].x, b[kt2].y);
                if (ch < DIN) {
                    float2 bv = *(const float2*)(b2s + ch);
                    *(float2*)(outb + (size_t)(m * 16 + g)     * NOUTC + ch) =
                        make_float2(cc[0] + bv.x, cc[1] + bv.y);
                    *(float2*)(outb + (size_t)(m * 16 + g + 8) * NOUTC + ch) =
                        make_float2(cc[2] + bv.x, cc[3] + bv.y);
                }
            }
        }
        __syncwarp();
    }
}

extern "C" void kernel_launch(void* const* d_in, const int* in_sizes, int n_in,
                              void* d_out, int out_size)
{
    const float* pts     = (const float*)d_in[0];
    const float* feature = (const float*)d_in[1];
    const float* ind     = (const float*)d_in[2];
    const float* w1      = (const float*)d_in[3];
    const float* b1      = (const float*)d_in[4];
    const float* w2      = (const float*)d_in[5];
    const float* b2      = (const float*)d_in[6];
    float*       out     = (float*)d_out;

    const size_t smem = SMEM_FLOATS * sizeof(float);   // 98688 B -> 2 blocks/SM
    cudaFuncSetAttribute(v3d_mma_kernel,
                         cudaFuncAttributeMaxDynamicSharedMemorySize, (int)smem);

    dim3 grid(NP / (256 * NTILES), NJ);   // (32, 24)
    dim3 block(256);
    v3d_mma_kernel<<<grid, block, smem>>>(pts, feature, ind, w1, b1, w2, b2, out);
}

// round 15
// speedup vs baseline: 1.8096x; 1.1556x over previous
#include <cuda_runtime.h>
#include <cstdint>

#define NJ    24
#define NP    32768
#define NF    42
#define NR    16
#define DIN   126
#define HID   32
#define NIND  18
#define NOUTC 144

#define NKT   18           // K tiles (K padded to 144 = 3 * 48)
#define NTILES 4           // passes per block; pass = 256 pts (8 warps x 32)
#define SFP   52           // feature-line stride (kills xi bank conflicts)
#define VST   28           // V half-chunk stride (24 cols + 4 pad; full 32-bank spread)

// shared layout (floats)
#define OFF_VO   0                         // 8 warps * 32*28   = 7168
#define OFF_W1F  7168                      // 18kt*4nt*32*2     = 4608
#define OFF_W2F  11776                     // 4kt*16nt*32*2     = 4096
#define OFF_SF   15872                     // [c][r][SFP] 3*16*52 = 2496
#define OFF_B1   18368                     // 32
#define OFF_B2   18400                     // 128
#define SMEM_FLOATS 18528                  // 74112 B -> 3 blocks/SM (24 warps)

__device__ __forceinline__ uint32_t tf32r(float x) {
    uint32_t r; asm("cvt.rna.tf32.f32 %0, %1;" : "=r"(r) : "f"(x)); return r;
}

__device__ __forceinline__ void mma_tf32(float c[4], uint32_t a0, uint32_t a1,
                                         uint32_t a2, uint32_t a3,
                                         uint32_t b0, uint32_t b1) {
    asm volatile(
        "mma.sync.aligned.m16n8k8.row.col.f32.tf32.tf32.f32 "
        "{%0,%1,%2,%3}, {%4,%5,%6,%7}, {%8,%9}, {%0,%1,%2,%3};\n"
        : "+f"(c[0]), "+f"(c[1]), "+f"(c[2]), "+f"(c[3])
        : "r"(a0), "r"(a1), "r"(a2), "r"(a3), "r"(b0), "r"(b1));
}

extern "C" __global__ void __launch_bounds__(256, 3)
v3d_mma_kernel(const float* __restrict__ pts,
               const float* __restrict__ feature,
               const float* __restrict__ ind,
               const float* __restrict__ w1,
               const float* __restrict__ b1,
               const float* __restrict__ w2,
               const float* __restrict__ b2,
               float* __restrict__ out)
{
    extern __shared__ float sm[];
    float* sfeat = sm + OFF_SF;
    float* b1s   = sm + OFF_B1;
    float* b2s   = sm + OFF_B2;
    uint32_t* w1f = (uint32_t*)(sm + OFF_W1F);
    uint32_t* w2f = (uint32_t*)(sm + OFF_W2F);

    const int j    = blockIdx.y;
    const int tid  = threadIdx.x;
    const int lane = tid & 31;
    const int warp = tid >> 5;

    // ---------------- Stage per-volume constants (once per block) ----------------
    if (tid < HID) b1s[tid] = b1[j * HID + tid];
    if (tid < 128) b2s[tid] = (tid < DIN) ? b2[j * DIN + tid] : 0.0f;

    {   // W1 fragments over padded K=144 (col k = c*48+f), [kt][nt][lane]{b0,b1}
        const float* w1g = w1 + j * (DIN * HID);
        for (int idx = tid; idx < NKT * 128; idx += 256) {
            int kt = idx >> 7, rem = idx & 127;
            int nt = rem >> 5, ln = rem & 31;
            int tg = ln & 3, gg = ln >> 2;
            int n  = nt * 8 + gg;
            uint32_t v2[2];
            #pragma unroll
            for (int s = 0; s < 2; ++s) {
                int k = kt * 8 + tg + 4 * s;
                int c = k / 48, f = k - c * 48;
                v2[s] = (f < NF) ? tf32r(w1g[(f * 3 + c) * HID + n]) : 0u;
            }
            *(uint2*)(w1f + idx * 2) = make_uint2(v2[0], v2[1]);
        }
    }
    {   // W2 fragments: [kt2][nt][lane]{b0,b1}, N padded 126->128
        const float* w2g = w2 + j * (HID * DIN);
        for (int idx = tid; idx < 2048; idx += 256) {
            int kt2 = idx >> 9, rem = idx & 511;
            int nt = rem >> 5, ln = rem & 31;
            int tg = ln & 3, gg = ln >> 2;
            int k = kt2 * 8 + tg, n = nt * 8 + gg;
            uint32_t x = (n < DIN) ? tf32r(w2g[k * DIN + n])       : 0u;
            uint32_t y = (n < DIN) ? tf32r(w2g[(k + 4) * DIN + n]) : 0u;
            *(uint2*)(w2f + idx * 2) = make_uint2(x, y);
        }
    }
    {   // features [f][r][c] -> [c][r][f], row stride SFP=52 (conflict-spread)
        for (int idx = tid; idx < 3 * NR * SFP; idx += 256) sfeat[idx] = 0.0f;
        __syncthreads();
        const float* fg = feature + j * (NF * NR * 3);
        for (int idx = tid; idx < NF * NR * 3; idx += 256) {
            int f = idx / 48;
            int rr = (idx - f * 48) / 3;
            int c = idx - f * 48 - rr * 3;
            sfeat[(c * NR + rr) * SFP + f] = fg[idx];
        }
    }
    __syncthreads();

    uint32_t* Vu = (uint32_t*)(sm + OFF_VO) + warp * (32 * VST);

    const int tig = lane & 3;
    const int g   = lane >> 2;
    // shfl transpose source lanes (C-frag -> A-frag retarget, intra quad-of-4)
    const int srcA = (lane & 28) | (tig >> 1);
    const int srcB = srcA + 2;
    const bool odd = (tig & 1);

    // ================= Pass loop: 4 passes of 256 points (32 per warp) ==========
    #pragma unroll 1
    for (int t = 0; t < NTILES; ++t) {
        const int pw0 = (blockIdx.x * NTILES + t) * 256 + warp * 32;

        // lane's point (lane = point index within warp's 32)
        const float* pp = pts + ((size_t)j * NP + pw0 + lane) * 3;
        float pc[3] = {pp[0], pp[1], pp[2]};

        // ---------------- ind_feature copy early (overlaps compute) ----------
        {
            float*       outg = out + ((size_t)j * NP + pw0) * NOUTC;
            const float* indg = ind + ((size_t)j * NP + pw0) * NIND;
            #pragma unroll 1
            for (int idx = lane; idx < 32 * NIND; idx += 32) {
                int ppt = idx / NIND;
                int cc  = idx - ppt * NIND;
                outg[ppt * NOUTC + cc] = indg[idx];
            }
        }

        // ---------------- Layer 1 with half-chunked V generation --------------
        float c1r[2][4][4];
        #pragma unroll
        for (int m = 0; m < 2; ++m)
            #pragma unroll
            for (int nt = 0; nt < 4; ++nt)
                #pragma unroll
                for (int e = 0; e < 4; ++e) c1r[m][nt][e] = 0.0f;

        #pragma unroll
        for (int c = 0; c < 3; ++c) {
            float x = fminf(fmaxf(fmaf(pc[c], 7.5f, 7.5f), 0.0f), 15.0f);
            int xi = (int)x; if (xi > NR - 2) xi = NR - 2;
            float wc = x - (float)xi;
            const float* row = sfeat + (c * NR + xi) * SFP;
            uint32_t* vrow = Vu + lane * VST;

            #pragma unroll
            for (int h = 0; h < 2; ++h) {
                // --- generate half-chunk: 24 cols (f = h*24 .. h*24+23; zeros >=42)
                const float* rh = row + h * 24;
                #pragma unroll
                for (int i = 0; i < 6; ++i) {
                    float4 g0 = *(const float4*)(rh + i * 4);
                    float4 g1 = *(const float4*)(rh + SFP + i * 4);
                    uint4 vv;
                    vv.x = tf32r(fmaf(wc, g1.x - g0.x, g0.x));
                    vv.y = tf32r(fmaf(wc, g1.y - g0.y, g0.y));
                    vv.z = tf32r(fmaf(wc, g1.z - g0.z, g0.z));
                    vv.w = tf32r(fmaf(wc, g1.w - g0.w, g0.w));
                    *(uint4*)(vrow + i * 4) = vv;
                }
                __syncwarp();

                // --- consume: 3 kt steps; each B fragment feeds BOTH m-tiles
                #pragma unroll
                for (int ktl = 0; ktl < 3; ++ktl) {
                    int kt = c * 6 + h * 3 + ktl;
                    uint2 b[4];
                    #pragma unroll
                    for (int nt = 0; nt < 4; ++nt)
                        b[nt] = *(const uint2*)(w1f + ((kt * 4 + nt) * 32 + lane) * 2);
                    #pragma unroll
                    for (int m = 0; m < 2; ++m) {
                        const uint32_t* va = Vu + (m * 16 + g) * VST + ktl * 8 + tig;
                        uint32_t a0 = va[0];
                        uint32_t a1 = va[8 * VST];
                        uint32_t a2 = va[4];
                        uint32_t a3 = va[8 * VST + 4];
                        #pragma unroll
                        for (int nt = 0; nt < 4; ++nt)
                            mma_tf32(c1r[m][nt], a0, a1, a2, a3, b[nt].x, b[nt].y);
                    }
                }
                __syncwarp();   // half-chunk buffer reused (next h/c or next pass)
            }
        }

        // ---------------- bias + relu + tf32, then shfl-transpose to A-frags ---
        // C-frag: lane(g,t) holds H[g][nt*8+2t(+1)], H[g+8][...].
        // A-frag: lane(g,t) needs H[g(+8)][nt*8+t] and [nt*8+t+4].
        uint32_t ha[2][16];
        #pragma unroll
        for (int m = 0; m < 2; ++m) {
            uint32_t hb[16];
            #pragma unroll
            for (int nt = 0; nt < 4; ++nt) {
                float2 bb = *(const float2*)(b1s + nt * 8 + 2 * tig);
                hb[nt * 4 + 0] = tf32r(fmaxf(c1r[m][nt][0] + bb.x, 0.0f));
                hb[nt * 4 + 1] = tf32r(fmaxf(c1r[m][nt][1] + bb.y, 0.0f));
                hb[nt * 4 + 2] = tf32r(fmaxf(c1r[m][nt][2] + bb.x, 0.0f));
                hb[nt * 4 + 3] = tf32r(fmaxf(c1r[m][nt][3] + bb.y, 0.0f));
            }
            #pragma unroll
            for (int nt = 0; nt < 4; ++nt) {
                uint32_t e0 = hb[nt * 4 + 0], e1 = hb[nt * 4 + 1];
                uint32_t e2 = hb[nt * 4 + 2], e3 = hb[nt * 4 + 3];
                uint32_t u0 = __shfl_sync(0xffffffffu, e0, srcA);
                uint32_t u1 = __shfl_sync(0xffffffffu, e1, srcA);
                uint32_t v0 = __shfl_sync(0xffffffffu, e2, srcA);
                uint32_t v1 = __shfl_sync(0xffffffffu, e3, srcA);
                uint32_t w0 = __shfl_sync(0xffffffffu, e0, srcB);
                uint32_t w1v = __shfl_sync(0xffffffffu, e1, srcB);
                uint32_t x0 = __shfl_sync(0xffffffffu, e2, srcB);
                uint32_t x1 = __shfl_sync(0xffffffffu, e3, srcB);
                ha[m][nt * 4 + 0] = odd ? u1 : u0;
                ha[m][nt * 4 + 1] = odd ? v1 : v0;
                ha[m][nt * 4 + 2] = odd ? w1v : w0;
                ha[m][nt * 4 + 3] = odd ? x1 : x0;
            }
        }

        // ---------------- Layer 2 MMAs + direct STG epilogue ------------------
        float* outb = out + ((size_t)j * NP + pw0) * NOUTC + NIND;
        #pragma unroll 2
        for (int nt2 = 0; nt2 < 16; ++nt2) {
            uint2 b[4];
            #pragma unroll
            for (int kt2 = 0; kt2 < 4; ++kt2)
                b[kt2] = *(const uint2*)(w2f + ((kt2 * 16 + nt2) * 32 + lane) * 2);
            int ch = nt2 * 8 + 2 * tig;
            #pragma unroll
            for (int m = 0; m < 2; ++m) {
                float cc[4] = {0.0f, 0.0f, 0.0f, 0.0f};
                #pragma unroll
                for (int kt2 = 0; kt2 < 4; ++kt2)
                    mma_tf32(cc, ha[m][kt2 * 4 + 0], ha[m][kt2 * 4 + 1],
                                 ha[m][kt2 * 4 + 2], ha[m][kt2 * 4 + 3],
                                 b[kt2].x, b[kt2].y);
                if (ch < DIN) {
                    float2 bv = *(const float2*)(b2s + ch);
                    *(float2*)(outb + (size_t)(m * 16 + g)     * NOUTC + ch) =
                        make_float2(cc[0] + bv.x, cc[1] + bv.y);
                    *(float2*)(outb + (size_t)(m * 16 + g + 8) * NOUTC + ch) =
                        make_float2(cc[2] + bv.x, cc[3] + bv.y);
                }
            }
        }
        __syncwarp();
    }
}

extern "C" void kernel_launch(void* const* d_in, const int* in_sizes, int n_in,
                              void* d_out, int out_size)
{
    const float* pts     = (const float*)d_in[0];
    const float* feature = (const float*)d_in[1];
    const float* ind     = (const float*)d_in[2];
    const float* w1      = (const float*)d_in[3];
    const float* b1      = (const float*)d_in[4];
    const float* w2      = (const float*)d_in[5];
    const float* b2      = (const float*)d_in[6];
    float*       out     = (float*)d_out;

    const size_t smem = SMEM_FLOATS * sizeof(float);   // 74112 B -> 3 blocks/SM
    cudaFuncSetAttribute(v3d_mma_kernel,
                         cudaFuncAttributeMaxDynamicSharedMemorySize, (int)smem);

    dim3 grid(NP / (256 * NTILES), NJ);   // (32, 24)
    dim3 block(256);
    v3d_mma_kernel<<<grid, block, smem>>>(pts, feature, ind, w1, b1, w2, b2, out);
}

// round 17
// speedup vs baseline: 1.8519x; 1.0234x over previous
#include <cuda_runtime.h>
#include <cstdint>

#define NJ    24
#define NP    32768
#define NF    42
#define NR    16
#define DIN   126
#define HID   32
#define NIND  18
#define NOUTC 144

#define NKT   18           // K tiles (K padded to 144 = 3 * 48)
#define SFP   52           // feature-line stride (kills xi bank conflicts)
#define VST   28           // V half-chunk stride (24 cols + 4 pad; full 32-bank spread)
#define NITEMS (NJ * 128)  // 3072 work items; item = 256 points of one volume

// shared layout (floats)
#define OFF_VO   0                         // 8 warps * 32*28   = 7168
#define OFF_W1F  7168                      // 18kt*4nt*32*2     = 4608
#define OFF_W2F  11776                     // 4kt*16nt*32*2     = 4096
#define OFF_SF   15872                     // [c][r][SFP] 3*16*52 = 2496
#define OFF_B1   18368                     // 32
#define OFF_B2   18400                     // 128
#define SMEM_FLOATS 18528                  // 74112 B -> 3 blocks/SM (24 warps)

__device__ __forceinline__ uint32_t tf32r(float x) {
    uint32_t r; asm("cvt.rna.tf32.f32 %0, %1;" : "=r"(r) : "f"(x)); return r;
}

__device__ __forceinline__ void mma_tf32(float c[4], uint32_t a0, uint32_t a1,
                                         uint32_t a2, uint32_t a3,
                                         uint32_t b0, uint32_t b1) {
    asm volatile(
        "mma.sync.aligned.m16n8k8.row.col.f32.tf32.tf32.f32 "
        "{%0,%1,%2,%3}, {%4,%5,%6,%7}, {%8,%9}, {%0,%1,%2,%3};\n"
        : "+f"(c[0]), "+f"(c[1]), "+f"(c[2]), "+f"(c[3])
        : "r"(a0), "r"(a1), "r"(a2), "r"(a3), "r"(b0), "r"(b1));
}

extern "C" __global__ void __launch_bounds__(256, 3)
v3d_mma_kernel(const float* __restrict__ pts,
               const float* __restrict__ feature,
               const float* __restrict__ ind,
               const float* __restrict__ w1,
               const float* __restrict__ b1,
               const float* __restrict__ w2,
               const float* __restrict__ b2,
               float* __restrict__ out)
{
    extern __shared__ float sm[];
    float* sfeat = sm + OFF_SF;
    float* b1s   = sm + OFF_B1;
    float* b2s   = sm + OFF_B2;
    uint32_t* w1f = (uint32_t*)(sm + OFF_W1F);
    uint32_t* w2f = (uint32_t*)(sm + OFF_W2F);

    const int tid  = threadIdx.x;
    const int lane = tid & 31;
    const int warp = tid >> 5;

    uint32_t* Vu = (uint32_t*)(sm + OFF_VO) + warp * (32 * VST);

    const int tig = lane & 3;
    const int g   = lane >> 2;
    // shfl transpose source lanes (C-frag -> A-frag retarget, intra quad-of-4)
    const int srcA = (lane & 28) | (tig >> 1);
    const int srcB = srcA + 2;
    const bool odd = (tig & 1);

    // ---- persistent work range: contiguous items, j-major ----
    const int G  = gridDim.x;
    const int i0 = (int)(((long long)blockIdx.x * NITEMS) / G);
    const int i1 = (int)(((long long)(blockIdx.x + 1) * NITEMS) / G);
    int jcur = -1;

    #pragma unroll 1
    for (int item = i0; item < i1; ++item) {
        const int j    = item >> 7;        // volume
        const int tile = item & 127;       // 256-pt tile within volume

        // ---------------- (Re)stage per-volume constants --------------------
        if (j != jcur) {
            __syncthreads();               // all warps done with prior smem use
            if (tid < HID) b1s[tid] = b1[j * HID + tid];
            if (tid < 128) b2s[tid] = (tid < DIN) ? b2[j * DIN + tid] : 0.0f;

            {   // W1 fragments over padded K=144 (col k = c*48+f)
                const float* w1g = w1 + j * (DIN * HID);
                for (int idx = tid; idx < NKT * 128; idx += 256) {
                    int kt = idx >> 7, rem = idx & 127;
                    int nt = rem >> 5, ln = rem & 31;
                    int tg = ln & 3, gg = ln >> 2;
                    int n  = nt * 8 + gg;
                    uint32_t v2[2];
                    #pragma unroll
                    for (int s = 0; s < 2; ++s) {
                        int k = kt * 8 + tg + 4 * s;
                        int c = k / 48, f = k - c * 48;
                        v2[s] = (f < NF) ? tf32r(w1g[(f * 3 + c) * HID + n]) : 0u;
                    }
                    *(uint2*)(w1f + idx * 2) = make_uint2(v2[0], v2[1]);
                }
            }
            {   // W2 fragments: [kt2][nt][lane]{b0,b1}, N padded 126->128
                const float* w2g = w2 + j * (HID * DIN);
                for (int idx = tid; idx < 2048; idx += 256) {
                    int kt2 = idx >> 9, rem = idx & 511;
                    int nt = rem >> 5, ln = rem & 31;
                    int tg = ln & 3, gg = ln >> 2;
                    int k = kt2 * 8 + tg, n = nt * 8 + gg;
                    uint32_t x = (n < DIN) ? tf32r(w2g[k * DIN + n])       : 0u;
                    uint32_t y = (n < DIN) ? tf32r(w2g[(k + 4) * DIN + n]) : 0u;
                    *(uint2*)(w2f + idx * 2) = make_uint2(x, y);
                }
            }
            {   // features [f][r][c] -> [c][r][f], row stride SFP=52
                for (int idx = tid; idx < 3 * NR * SFP; idx += 256) sfeat[idx] = 0.0f;
                __syncthreads();
                const float* fg = feature + j * (NF * NR * 3);
                for (int idx = tid; idx < NF * NR * 3; idx += 256) {
                    int f = idx / 48;
                    int rr = (idx - f * 48) / 3;
                    int c = idx - f * 48 - rr * 3;
                    sfeat[(c * NR + rr) * SFP + f] = fg[idx];
                }
            }
            __syncthreads();
            jcur = j;
        }

        const int pw0 = tile * 256 + warp * 32;

        // lane's point (lane = point index within warp's 32)
        const float* pp = pts + ((size_t)j * NP + pw0 + lane) * 3;
        float pc[3] = {pp[0], pp[1], pp[2]};

        // ---------------- ind_feature copy early (overlaps compute) ----------
        {
            float*       outg = out + ((size_t)j * NP + pw0) * NOUTC;
            const float* indg = ind + ((size_t)j * NP + pw0) * NIND;
            #pragma unroll 1
            for (int idx = lane; idx < 32 * NIND; idx += 32) {
                int ppt = idx / NIND;
                int cc  = idx - ppt * NIND;
                outg[ppt * NOUTC + cc] = indg[idx];
            }
        }

        // ---------------- Layer 1 with half-chunked V generation --------------
        float c1r[2][4][4];
        #pragma unroll
        for (int m = 0; m < 2; ++m)
            #pragma unroll
            for (int nt = 0; nt < 4; ++nt)
                #pragma unroll
                for (int e = 0; e < 4; ++e) c1r[m][nt][e] = 0.0f;

        #pragma unroll
        for (int c = 0; c < 3; ++c) {
            float x = fminf(fmaxf(fmaf(pc[c], 7.5f, 7.5f), 0.0f), 15.0f);
            int xi = (int)x; if (xi > NR - 2) xi = NR - 2;
            float wc = x - (float)xi;
            const float* row = sfeat + (c * NR + xi) * SFP;
            uint32_t* vrow = Vu + lane * VST;

            #pragma unroll
            for (int h = 0; h < 2; ++h) {
                // --- generate half-chunk: 24 cols (f = h*24 .. h*24+23)
                const float* rh = row + h * 24;
                #pragma unroll
                for (int i = 0; i < 6; ++i) {
                    float4 g0 = *(const float4*)(rh + i * 4);
                    float4 g1 = *(const float4*)(rh + SFP + i * 4);
                    uint4 vv;
                    vv.x = tf32r(fmaf(wc, g1.x - g0.x, g0.x));
                    vv.y = tf32r(fmaf(wc, g1.y - g0.y, g0.y));
                    vv.z = tf32r(fmaf(wc, g1.z - g0.z, g0.z));
                    vv.w = tf32r(fmaf(wc, g1.w - g0.w, g0.w));
                    *(uint4*)(vrow + i * 4) = vv;
                }
                __syncwarp();

                // --- consume: 3 kt steps; each B fragment feeds BOTH m-tiles
                #pragma unroll
                for (int ktl = 0; ktl < 3; ++ktl) {
                    int kt = c * 6 + h * 3 + ktl;
                    uint2 b[4];
                    #pragma unroll
                    for (int nt = 0; nt < 4; ++nt)
                        b[nt] = *(const uint2*)(w1f + ((kt * 4 + nt) * 32 + lane) * 2);
                    #pragma unroll
                    for (int m = 0; m < 2; ++m) {
                        const uint32_t* va = Vu + (m * 16 + g) * VST + ktl * 8 + tig;
                        uint32_t a0 = va[0];
                        uint32_t a1 = va[8 * VST];
                        uint32_t a2 = va[4];
                        uint32_t a3 = va[8 * VST + 4];
                        #pragma unroll
                        for (int nt = 0; nt < 4; ++nt)
                            mma_tf32(c1r[m][nt], a0, a1, a2, a3, b[nt].x, b[nt].y);
                    }
                }
                __syncwarp();   // half-chunk buffer reused (next h/c or next item)
            }
        }

        // ---------------- bias + relu + tf32, then shfl-transpose to A-frags ---
        uint32_t ha[2][16];
        #pragma unroll
        for (int m = 0; m < 2; ++m) {
            uint32_t hb[16];
            #pragma unroll
            for (int nt = 0; nt < 4; ++nt) {
                float2 bb = *(const float2*)(b1s + nt * 8 + 2 * tig);
                hb[nt * 4 + 0] = tf32r(fmaxf(c1r[m][nt][0] + bb.x, 0.0f));
                hb[nt * 4 + 1] = tf32r(fmaxf(c1r[m][nt][1] + bb.y, 0.0f));
                hb[nt * 4 + 2] = tf32r(fmaxf(c1r[m][nt][2] + bb.x, 0.0f));
                hb[nt * 4 + 3] = tf32r(fmaxf(c1r[m][nt][3] + bb.y, 0.0f));
            }
            #pragma unroll
            for (int nt = 0; nt < 4; ++nt) {
                uint32_t e0 = hb[nt * 4 + 0], e1 = hb[nt * 4 + 1];
                uint32_t e2 = hb[nt * 4 + 2], e3 = hb[nt * 4 + 3];
                uint32_t u0 = __shfl_sync(0xffffffffu, e0, srcA);
                uint32_t u1 = __shfl_sync(0xffffffffu, e1, srcA);
                uint32_t v0 = __shfl_sync(0xffffffffu, e2, srcA);
                uint32_t v1 = __shfl_sync(0xffffffffu, e3, srcA);
                uint32_t w0 = __shfl_sync(0xffffffffu, e0, srcB);
                uint32_t w1v = __shfl_sync(0xffffffffu, e1, srcB);
                uint32_t x0 = __shfl_sync(0xffffffffu, e2, srcB);
                uint32_t x1 = __shfl_sync(0xffffffffu, e3, srcB);
                ha[m][nt * 4 + 0] = odd ? u1 : u0;
                ha[m][nt * 4 + 1] = odd ? v1 : v0;
                ha[m][nt * 4 + 2] = odd ? w1v : w0;
                ha[m][nt * 4 + 3] = odd ? x1 : x0;
            }
        }

        // ---------------- Layer 2 MMAs + direct STG epilogue ------------------
        float* outb = out + ((size_t)j * NP + pw0) * NOUTC + NIND;
        #pragma unroll 2
        for (int nt2 = 0; nt2 < 16; ++nt2) {
            uint2 b[4];
            #pragma unroll
            for (int kt2 = 0; kt2 < 4; ++kt2)
                b[kt2] = *(const uint2*)(w2f + ((kt2 * 16 + nt2) * 32 + lane) * 2);
            int ch = nt2 * 8 + 2 * tig;
            #pragma unroll
            for (int m = 0; m < 2; ++m) {
                float cc[4] = {0.0f, 0.0f, 0.0f, 0.0f};
                #pragma unroll
                for (int kt2 = 0; kt2 < 4; ++kt2)
                    mma_tf32(cc, ha[m][kt2 * 4 + 0], ha[m][kt2 * 4 + 1],
                                 ha[m][kt2 * 4 + 2], ha[m][kt2 * 4 + 3],
                                 b[kt2].x, b[kt2].y);
                if (ch < DIN) {
                    float2 bv = *(const float2*)(b2s + ch);
                    *(float2*)(outb + (size_t)(m * 16 + g)     * NOUTC + ch) =
                        make_float2(cc[0] + bv.x, cc[1] + bv.y);
                    *(float2*)(outb + (size_t)(m * 16 + g + 8) * NOUTC + ch) =
                        make_float2(cc[2] + bv.x, cc[3] + bv.y);
                }
            }
        }
        __syncwarp();
    }
}

extern "C" void kernel_launch(void* const* d_in, const int* in_sizes, int n_in,
                              void* d_out, int out_size)
{
    const float* pts     = (const float*)d_in[0];
    const float* feature = (const float*)d_in[1];
    const float* ind     = (const float*)d_in[2];
    const float* w1      = (const float*)d_in[3];
    const float* b1      = (const float*)d_in[4];
    const float* w2      = (const float*)d_in[5];
    const float* b2      = (const float*)d_in[6];
    float*       out     = (float*)d_out;

    const size_t smem = SMEM_FLOATS * sizeof(float);   // 74112 B -> 3 blocks/SM
    cudaFuncSetAttribute(v3d_mma_kernel,
                         cudaFuncAttributeMaxDynamicSharedMemorySize, (int)smem);

    int sms = 148;                                     // fallback
    cudaDeviceGetAttribute(&sms, cudaDevAttrMultiProcessorCount, 0);
    int grid = sms * 3;                                // exact residency, no tail
    if (grid > NITEMS) grid = NITEMS;

    v3d_mma_kernel<<<grid, 256, smem>>>(pts, feature, ind, w1, b1, w2, b2, out);
}